// round 15
// baseline (speedup 1.0000x reference)
#include <cuda_runtime.h>
#include <cstdint>

#define NB 128
#define NT 512
#define NE 128
#define NK 4
#define NNEG 64
#define TILE 64
#define NTH 256
#define NWARP 8
#define NBLK (NB * (NT / TILE))   // 1024 blocks

// smem layout (bytes); 144B row stride => conflict-free ldmatrix AND row-major LDS.128
#define ROWB 144
#define NEGT_OFF 0                              // 64 x 144 = 9216
#define CE_OFF   9216
#define CE_STEP  (TILE * ROWB + 16)             // 9232: +16 de-aliases step dim banks
#define BQ_OFF   (CE_OFF + 4 * CE_STEP)         // 46144: 67 quantized base rows
#define NBQ      (TILE + 3)                     // 67
#define SEB_OFF  (BQ_OFF + NBQ * ROWB)          // 55792: [64 pos][4] float
#define SUM_OFF  (SEB_OFF + TILE * 16)          // 56816
#define SMEM_BYTES (SUM_OFF + 32)               // 56848

#define QI 25.4f          // 127/5
#define QS (5.0f / 127.0f)

__device__ double g_part[NBLK][NK];   // per-block partials (overwritten every replay)
__device__ unsigned int g_ctr;        // zero-init; last block resets each replay

// Packed saturating quantizer: x -> byte0 .. w -> byte3
__device__ __forceinline__ uint32_t q8x4(float x, float y, float z, float w) {
    int ix = __float2int_rn(x * QI), iy = __float2int_rn(y * QI);
    int iz = __float2int_rn(z * QI), iw = __float2int_rn(w * QI);
    uint32_t zero = 0u, hi, r;
    asm("cvt.pack.sat.s8.s32.b32 %0, %1, %2, %3;" : "=r"(hi) : "r"(iw), "r"(iz), "r"(zero));
    asm("cvt.pack.sat.s8.s32.b32 %0, %1, %2, %3;" : "=r"(r)  : "r"(iy), "r"(ix), "r"(hi));
    return r;
}

__device__ __forceinline__ void ldsm4(uint32_t& a0, uint32_t& a1, uint32_t& a2,
                                      uint32_t& a3, uint32_t addr) {
    asm volatile("ldmatrix.sync.aligned.m8n8.x4.shared.b16 {%0,%1,%2,%3}, [%4];"
                 : "=r"(a0), "=r"(a1), "=r"(a2), "=r"(a3) : "r"(addr));
}
__device__ __forceinline__ void ldsm2(uint32_t& b0, uint32_t& b1, uint32_t addr) {
    asm volatile("ldmatrix.sync.aligned.m8n8.x2.shared.b16 {%0,%1}, [%2];"
                 : "=r"(b0), "=r"(b1) : "r"(addr));
}
__device__ __forceinline__ void imma(int* d, uint32_t a0, uint32_t a1, uint32_t a2,
                                     uint32_t a3, uint32_t b0, uint32_t b1) {
    asm volatile("mma.sync.aligned.m16n8k32.row.col.s32.s8.s8.s32 "
                 "{%0,%1,%2,%3}, {%4,%5,%6,%7}, {%8,%9}, {%0,%1,%2,%3};"
                 : "+r"(d[0]), "+r"(d[1]), "+r"(d[2]), "+r"(d[3])
                 : "r"(a0), "r"(a1), "r"(a2), "r"(a3), "r"(b0), "r"(b1));
}

__global__ __launch_bounds__(NTH, 4) void cpc_imma(
    const float* __restrict__ base,       // [B, T, E]
    const float* __restrict__ mc,         // [B, T, E, K]
    const int*   __restrict__ seq_lens,   // [B]
    const int*   __restrict__ sample_ids, // [B, NNEG]
    float* __restrict__ out, int out_size)
{
    extern __shared__ char smem[];
    const int bid  = blockIdx.x;
    const int b    = bid & (NB - 1);            // LPT: tile-major launch order
    const int t0   = (bid >> 7) * TILE;
    const int tid  = threadIdx.x;
    const int w    = tid >> 5;
    const int lane = tid & 31;
    const int seqlen = seq_lens[b];
    const double LOG65D = 4.174387269895637;
    const float  LOG65  = 4.17438727f;

    if (t0 >= seqlen) {
        if (tid == 0) {
            #pragma unroll
            for (int i = 0; i < NK; ++i) {
                int cnt = NT - 1 - i - t0;
                if (cnt > TILE) cnt = TILE;
                if (cnt < 0) cnt = 0;
                g_part[bid][i] = (double)cnt * LOG65D;
            }
        }
    } else {
        const uint32_t sb = (uint32_t)__cvta_generic_to_shared(smem);

        ((float*)(smem + SEB_OFF))[tid] = 0.f;     // TILE*4 == NTH
        if (tid < NK) ((float*)(smem + SUM_OFF))[tid] = 0.f;

        // ---- Zero-fill ce rows of masked positions (logit 0, discarded later)
        const int mstart = (seqlen - t0 < TILE) ? (seqlen - t0) : TILE;
        const int nzrows = TILE - mstart;
        for (int idx = tid; idx < 4 * nzrows * 36; idx += NTH) {
            int st = idx / (nzrows * 36);
            int rem = idx - st * nzrows * 36;
            int row = mstart + rem / 36;
            int word = rem - (rem / 36) * 36;
            *(uint32_t*)(smem + CE_OFF + st * CE_STEP + row * ROWB + word * 4) = 0u;
        }

        // ---- Gather + quantize negatives: NEGT[n][word m]
        for (int idx = tid; idx < NNEG * 32; idx += NTH) {
            int n = idx >> 5, m = idx & 31;
            float4 v = ((const float4*)(base + (size_t)sample_ids[b * NNEG + n] * NE))[m];
            *(uint32_t*)(smem + NEGT_OFF + n * ROWB + m * 4) = q8x4(v.x, v.y, v.z, v.w);
        }

        // ---- Quantize base tile rows t0+1 .. t0+NBQ (for positive dots)
        for (int idx = tid; idx < NBQ * 32; idx += NTH) {
            int j = idx >> 5, m = idx & 31;
            int gr = t0 + 1 + j;
            if (gr < NT) {
                float4 v = ((const float4*)(base + (size_t)(b * NT + gr) * NE))[m];
                *(uint32_t*)(smem + BQ_OFF + j * ROWB + m * 4) = q8x4(v.x, v.y, v.z, v.w);
            }
        }

        // ---- Prep: warp w -> positions w*8..w*8+7; lane owns e=4*lane..+3.
        // Minimal chain: 4 LDG.128 -> 4 packs -> 4 STS.32 (no positives here).
        const float4* mc4 = (const float4*)mc;
        #pragma unroll 2
        for (int p = 0; p < 8; ++p) {
            const int r = w * 8 + p;
            const int s = t0 + r;
            if (s >= seqlen) continue;            // warp-uniform

            const float4* src = mc4 + (size_t)(b * NT + s) * NE + 4 * lane;
            float4 c0 = src[0], c1 = src[1], c2 = src[2], c3 = src[3];

            *(uint32_t*)(smem + CE_OFF + 0 * CE_STEP + r * ROWB + lane * 4) = q8x4(c0.x, c1.x, c2.x, c3.x);
            *(uint32_t*)(smem + CE_OFF + 1 * CE_STEP + r * ROWB + lane * 4) = q8x4(c0.y, c1.y, c2.y, c3.y);
            *(uint32_t*)(smem + CE_OFF + 2 * CE_STEP + r * ROWB + lane * 4) = q8x4(c0.z, c1.z, c2.z, c3.z);
            *(uint32_t*)(smem + CE_OFF + 3 * CE_STEP + r * ROWB + lane * 4) = q8x4(c0.w, c1.w, c2.w, c3.w);
        }
        __syncthreads();

        // ---- IMMA: warp = (ptile pt = w&3, neg-group wg = w>>2 -> 32 negs)
        const int pt = w & 3;
        const int wg = w >> 2;
        const int g   = lane >> 2;
        const int tig = lane & 3;
        const float S2 = QS * QS;

        const int arow  = ((lane >> 3) & 1) * 8 + (lane & 7);
        const int aboff = (lane >> 4) * 16;
        const int brow  = lane & 7;
        const int bboff = ((lane >> 3) & 1) * 16;

        #pragma unroll 1
        for (int st = 0; st < 4; ++st) {
            int d[4][4];
            #pragma unroll
            for (int nt = 0; nt < 4; ++nt)
                #pragma unroll
                for (int i = 0; i < 4; ++i) d[nt][i] = 0;

            uint32_t abase = sb + CE_OFF + st * CE_STEP + (pt * 16 + arow) * ROWB + aboff;
            uint32_t bbase = sb + NEGT_OFF + (wg * 32 + brow) * ROWB + bboff;

            #pragma unroll
            for (int kt = 0; kt < 4; ++kt) {
                uint32_t a0, a1, a2, a3;
                ldsm4(a0, a1, a2, a3, abase + kt * 32);
                #pragma unroll
                for (int nt = 0; nt < 4; ++nt) {
                    uint32_t b0, b1;
                    ldsm2(b0, b1, bbase + nt * 8 * ROWB + kt * 32);
                    imma(d[nt], a0, a1, a2, a3, b0, b1);
                }
            }

            float p0 = 0.f, p1 = 0.f;
            #pragma unroll
            for (int nt = 0; nt < 4; ++nt) {
                p0 += __expf((float)d[nt][0] * S2) + __expf((float)d[nt][1] * S2);
                p1 += __expf((float)d[nt][2] * S2) + __expf((float)d[nt][3] * S2);
            }
            p0 += __shfl_xor_sync(0xffffffffu, p0, 1);
            p0 += __shfl_xor_sync(0xffffffffu, p0, 2);
            p1 += __shfl_xor_sync(0xffffffffu, p1, 1);
            p1 += __shfl_xor_sync(0xffffffffu, p1, 2);
            if (tig == 0) {
                atomicAdd((float*)(smem + SEB_OFF + (pt * 16 + g) * 16 + st * 4), p0);
                atomicAdd((float*)(smem + SEB_OFF + (pt * 16 + g + 8) * 16 + st * 4), p1);
            }
        }
        __syncthreads();

        // ---- Epilogue: thread (i = tid>>6, r = tid&63); warp == one step.
        // Positive via dp4a on quantized ce x quantized base (row j = r+i in BQ).
        {
            const int ei = tid >> 6;
            const int er = tid & 63;
            const int s  = t0 + er;

            const int4* cep = (const int4*)(smem + CE_OFF + ei * CE_STEP + er * ROWB);
            const int4* bqp = (const int4*)(smem + BQ_OFF + (er + ei) * ROWB);
            int pa = 0;
            #pragma unroll
            for (int k = 0; k < 8; ++k) {
                int4 a = cep[k];                   // conflict-free (stride 36 words)
                int4 q = bqp[k];
                pa = __dp4a(a.x, q.x, pa);
                pa = __dp4a(a.y, q.y, pa);
                pa = __dp4a(a.z, q.z, pa);
                pa = __dp4a(a.w, q.w, pa);
            }
            float pos = (float)pa * S2;
            float se  = ((const float*)(smem + SEB_OFF))[er * 4 + ei];

            float v = 0.f;
            if (s < NT - 1 - ei)
                v = (s < seqlen) ? (__logf(se + __expf(pos)) - pos) : LOG65;

            #pragma unroll
            for (int o = 16; o > 0; o >>= 1)
                v += __shfl_xor_sync(0xffffffffu, v, o);
            if (lane == 0)
                atomicAdd((float*)(smem + SUM_OFF) + ei, v);
        }
        __syncthreads();
        if (tid < NK)
            g_part[bid][tid] = (double)((const float*)(smem + SUM_OFF))[tid];
    }

    // ---- Last block finalizes
    __threadfence();
    __shared__ unsigned int s_last;
    if (tid == 0) s_last = (atomicAdd(&g_ctr, 1u) == (unsigned)(NBLK - 1));
    __syncthreads();
    if (!s_last) return;

    __shared__ double ssum[NK];
    if (tid < NK) ssum[tid] = 0.0;
    __syncthreads();

    double acc2[NK] = {0.0, 0.0, 0.0, 0.0};
    for (int r = tid; r < NBLK; r += NTH) {
        #pragma unroll
        for (int i = 0; i < NK; ++i) acc2[i] += g_part[r][i];
    }
    #pragma unroll
    for (int i = 0; i < NK; ++i) {
        #pragma unroll
        for (int o = 16; o > 0; o >>= 1)
            acc2[i] += __shfl_xor_sync(0xffffffffu, acc2[i], o);
    }
    if ((tid & 31) == 0) {
        #pragma unroll
        for (int i = 0; i < NK; ++i) atomicAdd(&ssum[i], acc2[i]);
    }
    __syncthreads();

    if (tid == 0) {
        double t = 0.0;
        #pragma unroll
        for (int i = 0; i < NK; ++i)
            t += ssum[i] / ((double)NB * (double)(NT - (i + 1)));
        out[0] = (float)(t / NK);
        g_ctr = 0;                      // reset for next replay
    }
    for (int j = tid + 1; j < out_size; j += NTH) out[j] = out[0];
}

extern "C" void kernel_launch(void* const* d_in, const int* in_sizes, int n_in,
                              void* d_out, int out_size) {
    const float* base = (const float*)d_in[0];
    const float* mc   = (const float*)d_in[1];
    const int*   seq  = (const int*)d_in[2];
    const int*   sid  = (const int*)d_in[3];

    cudaFuncSetAttribute(cpc_imma, cudaFuncAttributeMaxDynamicSharedMemorySize, SMEM_BYTES);

    cpc_imma<<<NBLK, NTH, SMEM_BYTES>>>(base, mc, seq, sid, (float*)d_out, out_size);
}

// round 16
// speedup vs baseline: 1.0433x; 1.0433x over previous
#include <cuda_runtime.h>
#include <cstdint>

#define NB 128
#define NT 512
#define NE 128
#define NK 4
#define NNEG 64
#define TILE 64
#define NTH 256
#define NWARP 8
#define NBLK (NB * (NT / TILE))   // 1024 blocks

// smem layout (bytes); 144B row stride => conflict-free ldmatrix AND row-major LDS.128
#define ROWB 144
#define NEGT_OFF 0                              // 64 x 144 = 9216
#define CE_OFF   9216
#define CE_STEP  (TILE * ROWB + 16)             // 9232: +16 de-aliases step dim banks
#define BQ_OFF   (CE_OFF + 4 * CE_STEP)         // 46144: 67 quantized base rows
#define NBQ      (TILE + 3)                     // 67
#define SEB_OFF  (BQ_OFF + NBQ * ROWB)          // 55792: [64 pos][4] float
#define SUM_OFF  (SEB_OFF + TILE * 16)          // 56816
#define SMEM_BYTES (SUM_OFF + 32)               // 56848

#define QI 25.4f          // 127/5
#define QS (5.0f / 127.0f)

__device__ double g_part[NBLK][NK];   // per-block partials (overwritten every replay)
__device__ unsigned int g_ctr;        // zero-init; last block resets each replay

// Packed saturating quantizer: x -> byte0 .. w -> byte3
__device__ __forceinline__ uint32_t q8x4(float x, float y, float z, float w) {
    int ix = __float2int_rn(x * QI), iy = __float2int_rn(y * QI);
    int iz = __float2int_rn(z * QI), iw = __float2int_rn(w * QI);
    uint32_t zero = 0u, hi, r;
    asm("cvt.pack.sat.s8.s32.b32 %0, %1, %2, %3;" : "=r"(hi) : "r"(iw), "r"(iz), "r"(zero));
    asm("cvt.pack.sat.s8.s32.b32 %0, %1, %2, %3;" : "=r"(r)  : "r"(iy), "r"(ix), "r"(hi));
    return r;
}

__device__ __forceinline__ void ldsm4(uint32_t& a0, uint32_t& a1, uint32_t& a2,
                                      uint32_t& a3, uint32_t addr) {
    asm volatile("ldmatrix.sync.aligned.m8n8.x4.shared.b16 {%0,%1,%2,%3}, [%4];"
                 : "=r"(a0), "=r"(a1), "=r"(a2), "=r"(a3) : "r"(addr));
}
__device__ __forceinline__ void ldsm2(uint32_t& b0, uint32_t& b1, uint32_t addr) {
    asm volatile("ldmatrix.sync.aligned.m8n8.x2.shared.b16 {%0,%1}, [%2];"
                 : "=r"(b0), "=r"(b1) : "r"(addr));
}
__device__ __forceinline__ void imma(int* d, uint32_t a0, uint32_t a1, uint32_t a2,
                                     uint32_t a3, uint32_t b0, uint32_t b1) {
    asm volatile("mma.sync.aligned.m16n8k32.row.col.s32.s8.s8.s32 "
                 "{%0,%1,%2,%3}, {%4,%5,%6,%7}, {%8,%9}, {%0,%1,%2,%3};"
                 : "+r"(d[0]), "+r"(d[1]), "+r"(d[2]), "+r"(d[3])
                 : "r"(a0), "r"(a1), "r"(a2), "r"(a3), "r"(b0), "r"(b1));
}

__global__ __launch_bounds__(NTH, 4) void cpc_imma(
    const float* __restrict__ base,       // [B, T, E]
    const float* __restrict__ mc,         // [B, T, E, K]
    const int*   __restrict__ seq_lens,   // [B]
    const int*   __restrict__ sample_ids, // [B, NNEG]
    float* __restrict__ out, int out_size)
{
    extern __shared__ char smem[];
    const int bid  = blockIdx.x;
    const int b    = bid & (NB - 1);            // LPT: tile-major launch order
    const int t0   = (bid >> 7) * TILE;
    const int tid  = threadIdx.x;
    const int w    = tid >> 5;
    const int lane = tid & 31;
    const int seqlen = seq_lens[b];
    const double LOG65D = 4.174387269895637;
    const float  LOG65  = 4.17438727f;

    if (t0 >= seqlen) {
        if (tid == 0) {
            #pragma unroll
            for (int i = 0; i < NK; ++i) {
                int cnt = NT - 1 - i - t0;
                if (cnt > TILE) cnt = TILE;
                if (cnt < 0) cnt = 0;
                g_part[bid][i] = (double)cnt * LOG65D;
            }
        }
    } else {
        const uint32_t sb = (uint32_t)__cvta_generic_to_shared(smem);
        const int mstart = (seqlen - t0 < TILE) ? (seqlen - t0) : TILE;

        // ---- Prep FIRST (the big DRAM stream): branchless loop over valid
        // rows only -> ptxas batches LDG.128s across unrolled iterations.
        {
            const float4* mc4 = (const float4*)mc;
            const int r0v = w * 8;
            int pmax = mstart - r0v;
            pmax = pmax < 0 ? 0 : (pmax > 8 ? 8 : pmax);
            const float4* srcw = mc4 + ((size_t)(b * NT + t0 + r0v) * NE) + 4 * lane;
            uint32_t dstw = (uint32_t)(CE_OFF + r0v * ROWB + lane * 4);

            #pragma unroll 2
            for (int p = 0; p < pmax; ++p) {
                const float4* src = srcw + (size_t)p * NE;
                float4 c0 = __ldcs(src + 0);
                float4 c1 = __ldcs(src + 1);
                float4 c2 = __ldcs(src + 2);
                float4 c3 = __ldcs(src + 3);
                uint32_t d0 = q8x4(c0.x, c1.x, c2.x, c3.x);
                uint32_t d1 = q8x4(c0.y, c1.y, c2.y, c3.y);
                uint32_t d2 = q8x4(c0.z, c1.z, c2.z, c3.z);
                uint32_t d3 = q8x4(c0.w, c1.w, c2.w, c3.w);
                uint32_t dst = dstw + (uint32_t)p * ROWB;
                *(uint32_t*)(smem + dst + 0 * CE_STEP) = d0;
                *(uint32_t*)(smem + dst + 1 * CE_STEP) = d1;
                *(uint32_t*)(smem + dst + 2 * CE_STEP) = d2;
                *(uint32_t*)(smem + dst + 3 * CE_STEP) = d3;
            }
        }

        ((float*)(smem + SEB_OFF))[tid] = 0.f;     // TILE*4 == NTH
        if (tid < NK) ((float*)(smem + SUM_OFF))[tid] = 0.f;

        // ---- Zero-fill ce rows of masked positions (logit 0, discarded later)
        const int nzrows = TILE - mstart;
        for (int idx = tid; idx < 4 * nzrows * 36; idx += NTH) {
            int st = idx / (nzrows * 36);
            int rem = idx - st * nzrows * 36;
            int row = mstart + rem / 36;
            int word = rem - (rem / 36) * 36;
            *(uint32_t*)(smem + CE_OFF + st * CE_STEP + row * ROWB + word * 4) = 0u;
        }

        // ---- Gather + quantize negatives: NEGT[n][word m]
        for (int idx = tid; idx < NNEG * 32; idx += NTH) {
            int n = idx >> 5, m = idx & 31;
            float4 v = ((const float4*)(base + (size_t)sample_ids[b * NNEG + n] * NE))[m];
            *(uint32_t*)(smem + NEGT_OFF + n * ROWB + m * 4) = q8x4(v.x, v.y, v.z, v.w);
        }

        // ---- Quantize base tile rows t0+1 .. t0+NBQ (for positive dots)
        for (int idx = tid; idx < NBQ * 32; idx += NTH) {
            int j = idx >> 5, m = idx & 31;
            int gr = t0 + 1 + j;
            if (gr < NT) {
                float4 v = ((const float4*)(base + (size_t)(b * NT + gr) * NE))[m];
                *(uint32_t*)(smem + BQ_OFF + j * ROWB + m * 4) = q8x4(v.x, v.y, v.z, v.w);
            }
        }
        __syncthreads();

        // ---- IMMA: warp = (ptile pt = w&3, neg-group wg = w>>2 -> 32 negs)
        const int pt = w & 3;
        const int wg = w >> 2;
        const int g   = lane >> 2;
        const int tig = lane & 3;
        const float S2 = QS * QS;

        const int arow  = ((lane >> 3) & 1) * 8 + (lane & 7);
        const int aboff = (lane >> 4) * 16;
        const int brow  = lane & 7;
        const int bboff = ((lane >> 3) & 1) * 16;

        #pragma unroll 1
        for (int st = 0; st < 4; ++st) {
            int d[4][4];
            #pragma unroll
            for (int nt = 0; nt < 4; ++nt)
                #pragma unroll
                for (int i = 0; i < 4; ++i) d[nt][i] = 0;

            uint32_t abase = sb + CE_OFF + st * CE_STEP + (pt * 16 + arow) * ROWB + aboff;
            uint32_t bbase = sb + NEGT_OFF + (wg * 32 + brow) * ROWB + bboff;

            #pragma unroll
            for (int kt = 0; kt < 4; ++kt) {
                uint32_t a0, a1, a2, a3;
                ldsm4(a0, a1, a2, a3, abase + kt * 32);
                #pragma unroll
                for (int nt = 0; nt < 4; ++nt) {
                    uint32_t b0, b1;
                    ldsm2(b0, b1, bbase + nt * 8 * ROWB + kt * 32);
                    imma(d[nt], a0, a1, a2, a3, b0, b1);
                }
            }

            float p0 = 0.f, p1 = 0.f;
            #pragma unroll
            for (int nt = 0; nt < 4; ++nt) {
                p0 += __expf((float)d[nt][0] * S2) + __expf((float)d[nt][1] * S2);
                p1 += __expf((float)d[nt][2] * S2) + __expf((float)d[nt][3] * S2);
            }
            p0 += __shfl_xor_sync(0xffffffffu, p0, 1);
            p0 += __shfl_xor_sync(0xffffffffu, p0, 2);
            p1 += __shfl_xor_sync(0xffffffffu, p1, 1);
            p1 += __shfl_xor_sync(0xffffffffu, p1, 2);
            if (tig == 0) {
                atomicAdd((float*)(smem + SEB_OFF + (pt * 16 + g) * 16 + st * 4), p0);
                atomicAdd((float*)(smem + SEB_OFF + (pt * 16 + g + 8) * 16 + st * 4), p1);
            }
        }
        __syncthreads();

        // ---- Epilogue: thread (i = tid>>6, r = tid&63); warp == one step.
        {
            const int ei = tid >> 6;
            const int er = tid & 63;
            const int s  = t0 + er;

            const int4* cep = (const int4*)(smem + CE_OFF + ei * CE_STEP + er * ROWB);
            const int4* bqp = (const int4*)(smem + BQ_OFF + (er + ei) * ROWB);
            int pa = 0;
            #pragma unroll
            for (int k = 0; k < 8; ++k) {
                int4 a = cep[k];
                int4 q = bqp[k];
                pa = __dp4a(a.x, q.x, pa);
                pa = __dp4a(a.y, q.y, pa);
                pa = __dp4a(a.z, q.z, pa);
                pa = __dp4a(a.w, q.w, pa);
            }
            float pos = (float)pa * S2;
            float se  = ((const float*)(smem + SEB_OFF))[er * 4 + ei];

            float v = 0.f;
            if (s < NT - 1 - ei)
                v = (s < seqlen) ? (__logf(se + __expf(pos)) - pos) : LOG65;

            #pragma unroll
            for (int o = 16; o > 0; o >>= 1)
                v += __shfl_xor_sync(0xffffffffu, v, o);
            if (lane == 0)
                atomicAdd((float*)(smem + SUM_OFF) + ei, v);
        }
        __syncthreads();
        if (tid < NK)
            g_part[bid][tid] = (double)((const float*)(smem + SUM_OFF))[tid];
    }

    // ---- Last block finalizes
    __threadfence();
    __shared__ unsigned int s_last;
    if (tid == 0) s_last = (atomicAdd(&g_ctr, 1u) == (unsigned)(NBLK - 1));
    __syncthreads();
    if (!s_last) return;

    __shared__ double ssum[NK];
    if (tid < NK) ssum[tid] = 0.0;
    __syncthreads();

    double acc2[NK] = {0.0, 0.0, 0.0, 0.0};
    for (int r = tid; r < NBLK; r += NTH) {
        #pragma unroll
        for (int i = 0; i < NK; ++i) acc2[i] += g_part[r][i];
    }
    #pragma unroll
    for (int i = 0; i < NK; ++i) {
        #pragma unroll
        for (int o = 16; o > 0; o >>= 1)
            acc2[i] += __shfl_xor_sync(0xffffffffu, acc2[i], o);
    }
    if ((tid & 31) == 0) {
        #pragma unroll
        for (int i = 0; i < NK; ++i) atomicAdd(&ssum[i], acc2[i]);
    }
    __syncthreads();

    if (tid == 0) {
        double t = 0.0;
        #pragma unroll
        for (int i = 0; i < NK; ++i)
            t += ssum[i] / ((double)NB * (double)(NT - (i + 1)));
        out[0] = (float)(t / NK);
        g_ctr = 0;                      // reset for next replay
    }
    for (int j = tid + 1; j < out_size; j += NTH) out[j] = out[0];
}

extern "C" void kernel_launch(void* const* d_in, const int* in_sizes, int n_in,
                              void* d_out, int out_size) {
    const float* base = (const float*)d_in[0];
    const float* mc   = (const float*)d_in[1];
    const int*   seq  = (const int*)d_in[2];
    const int*   sid  = (const int*)d_in[3];

    cudaFuncSetAttribute(cpc_imma, cudaFuncAttributeMaxDynamicSharedMemorySize, SMEM_BYTES);

    cpc_imma<<<NBLK, NTH, SMEM_BYTES>>>(base, mc, seq, sid, (float*)d_out, out_size);
}